// round 2
// baseline (speedup 1.0000x reference)
#include <cuda_runtime.h>
#include <math.h>

#define LN_EPS 1e-5f

// ---------------- scratch (device globals: no allocation allowed) ----------------
__device__ float g_CB0[128 * 512];     // codebook @ mla_w0
__device__ float g_MP0[64 * 512];      // map_pos_embed @ mla_w0
__device__ float g_AP0[8192 * 512];    // agent_pos_embed @ mla_w0 + mla_b0

// block-wide (128 threads) reduction of two floats; leaves result in s/s2 for all threads
__device__ __forceinline__ void blockReduce2_128(float& s, float& s2, float* red) {
#pragma unroll
    for (int off = 16; off > 0; off >>= 1) {
        s  += __shfl_xor_sync(0xffffffffu, s,  off);
        s2 += __shfl_xor_sync(0xffffffffu, s2, off);
    }
    int w = threadIdx.x >> 5;
    if ((threadIdx.x & 31) == 0) { red[w] = s; red[4 + w] = s2; }
    __syncthreads();
    s  = red[0] + red[1] + red[2] + red[3];
    s2 = red[4] + red[5] + red[6] + red[7];
    __syncthreads();
}

// ---------------- kernel 1: map_pos_embed MLP + projection through mla_w0 ----------------
// grid 64 (one per map position m), 128 threads
__global__ __launch_bounds__(128) void k_mp(
    const float* __restrict__ mpl,                 // [64,256]
    const float* __restrict__ w0, const float* __restrict__ b0,
    const float* __restrict__ g0, const float* __restrict__ t0,
    const float* __restrict__ w1, const float* __restrict__ b1,
    const float* __restrict__ W0mla)               // [128,512]
{
    __shared__ float xs[256];
    __shared__ float hs[128];
    __shared__ float mp[128];
    __shared__ float red[8];
    int m = blockIdx.x, j = threadIdx.x;
    xs[j]       = mpl[m * 256 + j];
    xs[128 + j] = mpl[m * 256 + 128 + j];
    __syncthreads();

    float z = b0[j];
#pragma unroll 8
    for (int i = 0; i < 256; i++) z = fmaf(xs[i], w0[i * 128 + j], z);
    float s = z, s2 = z * z;
    blockReduce2_128(s, s2, red);
    float mean = s * (1.f / 128.f);
    float var  = s2 * (1.f / 128.f) - mean * mean;
    float rs   = rsqrtf(var + LN_EPS);
    hs[j] = fmaxf((z - mean) * rs * g0[j] + t0[j], 0.f);
    __syncthreads();

    float z1 = b1[j];
#pragma unroll 8
    for (int i = 0; i < 128; i++) z1 = fmaf(hs[i], w1[i * 128 + j], z1);
    mp[j] = z1;
    __syncthreads();

#pragma unroll
    for (int q = 0; q < 4; q++) {
        int c = j + q * 128;
        float acc = 0.f;
#pragma unroll 8
        for (int i = 0; i < 128; i++) acc = fmaf(mp[i], W0mla[i * 512 + c], acc);
        g_MP0[m * 512 + c] = acc;
    }
}

// ---------------- kernel 2: codebook @ mla_w0 ----------------
// grid 128 (one per codebook row), 128 threads
__global__ __launch_bounds__(128) void k_cb(
    const float* __restrict__ tok,                 // [128,128]
    const float* __restrict__ W0mla)               // [128,512]
{
    __shared__ float cb[128];
    int lat = blockIdx.x, j = threadIdx.x;
    cb[j] = tok[lat * 128 + j];
    __syncthreads();
#pragma unroll
    for (int q = 0; q < 4; q++) {
        int c = j + q * 128;
        float acc = 0.f;
#pragma unroll 8
        for (int i = 0; i < 128; i++) acc = fmaf(cb[i], W0mla[i * 512 + c], acc);
        g_CB0[lat * 512 + c] = acc;
    }
}

// ---------------- kernel 3: agent_pos_emb MLP + projection, fold mla_b0 ----------------
// grid 8192 = bs*T, 128 threads
__global__ __launch_bounds__(128) void k_ape(
    const float* __restrict__ heading,             // [64,32,128]
    const float* __restrict__ position,            // [64,32,128,2]
    const float* __restrict__ w0, const float* __restrict__ b0,
    const float* __restrict__ g0, const float* __restrict__ t0,
    const float* __restrict__ w1, const float* __restrict__ b1,
    const float* __restrict__ g1, const float* __restrict__ t1,
    const float* __restrict__ w2, const float* __restrict__ b2,
    const float* __restrict__ W0mla, const float* __restrict__ b0mla)
{
    __shared__ float a1[128], a2[128], av[128], red[8];
    int bt = blockIdx.x;
    int b = bt >> 7, t = bt & 127;
    int j = threadIdx.x;

    float hd = heading[(b * 32) * 128 + t];
    float px = position[((b * 32) * 128 + t) * 2 + 0];
    float py = position[((b * 32) * 128 + t) * 2 + 1];
    float sh = sinf(hd), ch = cosf(hd);

    float z = b0[j];
    z = fmaf(px, w0[0 * 128 + j], z);
    z = fmaf(py, w0[1 * 128 + j], z);
    z = fmaf(hd, w0[2 * 128 + j], z);
    z = fmaf(sh, w0[3 * 128 + j], z);
    z = fmaf(ch, w0[4 * 128 + j], z);
    float s = z, s2 = z * z;
    blockReduce2_128(s, s2, red);
    float mean = s * (1.f / 128.f);
    float var  = s2 * (1.f / 128.f) - mean * mean;
    float rs   = rsqrtf(var + LN_EPS);
    a1[j] = fmaxf((z - mean) * rs * g0[j] + t0[j], 0.f);
    __syncthreads();

    float z1 = b1[j];
#pragma unroll 8
    for (int i = 0; i < 128; i++) z1 = fmaf(a1[i], w1[i * 128 + j], z1);
    s = z1; s2 = z1 * z1;
    blockReduce2_128(s, s2, red);
    mean = s * (1.f / 128.f);
    var  = s2 * (1.f / 128.f) - mean * mean;
    rs   = rsqrtf(var + LN_EPS);
    a2[j] = fmaxf((z1 - mean) * rs * g1[j] + t1[j], 0.f);
    __syncthreads();

    float z2 = b2[j];
#pragma unroll 8
    for (int i = 0; i < 128; i++) z2 = fmaf(a2[i], w2[i * 128 + j], z2);
    av[j] = z2;
    __syncthreads();

#pragma unroll
    for (int q = 0; q < 4; q++) {
        int c = j + q * 128;
        float acc = b0mla[c];
#pragma unroll 8
        for (int i = 0; i < 128; i++) acc = fmaf(av[i], W0mla[i * 512 + c], acc);
        g_AP0[bt * 512 + c] = acc;
    }
}

// ---------------- kernel 4: fused gather + LN + ReLU + GEMM (the 34.4 GMAC) ----------------
// grid 8192 (one per (b,t): exactly the 64 m-rows), 256 threads
// smem layout (floats): Hs[64*514] | Wp[64*128 packed pairs] | Aps[512] | gsm[512] | tsm[512]
#define S_H 514
#define SMEM_FLOATS (64 * S_H + 64 * 128 + 512 * 3)
#define SMEM_BYTES (SMEM_FLOATS * 4)

__device__ __forceinline__ void fma2(unsigned long long& d, unsigned long long a, unsigned long long b) {
    asm("fma.rn.f32x2 %0, %1, %2, %0;" : "+l"(d) : "l"(a), "l"(b));
}

__global__ __launch_bounds__(256) void k_main(
    const int* __restrict__ lat_idx,               // [64,128,64]
    const float* __restrict__ W1,                  // [512,128]
    const float* __restrict__ b1,                  // [128]
    const float* __restrict__ g0, const float* __restrict__ t0,  // [512]
    float* __restrict__ out)                       // [64,128,64,128]
{
    extern __shared__ float smem[];
    float* Hs  = smem;
    float* wp  = smem + 64 * S_H;
    float* Aps = wp + 64 * 128;
    float* gsm = Aps + 512;
    float* tsm = gsm + 512;

    int bt  = blockIdx.x;
    int tid = threadIdx.x;
    int w = tid >> 5, l = tid & 31;

    for (int i = tid; i < 512; i += 256) {
        Aps[i] = g_AP0[bt * 512 + i];
        gsm[i] = g0[i];
        tsm[i] = t0[i];
    }
    __syncthreads();

    // -------- phase 1: build H tile (64 rows x 512), each warp does 8 rows --------
#pragma unroll
    for (int mm = 0; mm < 8; mm++) {
        int m = w * 8 + mm;
        int lat = lat_idx[bt * 64 + m];
        const float* cb = g_CB0 + lat * 512;
        const float* mp = g_MP0 + m * 512;
        float y[16];
        float s = 0.f, s2 = 0.f;
#pragma unroll
        for (int q = 0; q < 16; q++) {
            int k = q * 32 + l;
            float v = cb[k] + mp[k] + Aps[k];
            y[q] = v; s += v; s2 += v * v;
        }
#pragma unroll
        for (int off = 16; off > 0; off >>= 1) {
            s  += __shfl_xor_sync(0xffffffffu, s,  off);
            s2 += __shfl_xor_sync(0xffffffffu, s2, off);
        }
        float mean = s * (1.f / 512.f);
        float var  = s2 * (1.f / 512.f) - mean * mean;
        float rs   = rsqrtf(var + LN_EPS);
#pragma unroll
        for (int q = 0; q < 16; q++) {
            int k = q * 32 + l;
            float h = (y[q] - mean) * rs * gsm[k] + tsm[k];
            Hs[m * S_H + k] = fmaxf(h, 0.f);
        }
    }
    __syncthreads();

    // -------- phase 2: H[64,512] @ W1[512,128] with packed f32x2 FMA --------
    int ty = tid >> 4;   // 0..15 -> rows 4*ty .. 4*ty+3
    int tx = tid & 15;   // cols tx + 16*q, q<8

    unsigned long long acc[4][8];
#pragma unroll
    for (int r = 0; r < 4; r++)
#pragma unroll
        for (int q = 0; q < 8; q++) acc[r][q] = 0ull;

    for (int kc = 0; kc < 8; kc++) {
        const float* Wg = W1 + kc * 64 * 128;
        // pack W chunk: wp pair (k even, k odd) per (k2, c)
        for (int idx = tid; idx < 32 * 128; idx += 256) {
            int k2 = idx >> 7, c = idx & 127;
            wp[idx * 2 + 0] = Wg[(2 * k2) * 128 + c];
            wp[idx * 2 + 1] = Wg[(2 * k2 + 1) * 128 + c];
        }
        __syncthreads();

        const float* hbase = Hs + kc * 64;
#pragma unroll
        for (int k2 = 0; k2 < 32; k2++) {
            unsigned long long aa[4], bb[8];
#pragma unroll
            for (int r = 0; r < 4; r++)
                aa[r] = *reinterpret_cast<const unsigned long long*>(&hbase[(4 * ty + r) * S_H + 2 * k2]);
#pragma unroll
            for (int q = 0; q < 8; q++)
                bb[q] = *reinterpret_cast<const unsigned long long*>(&wp[(k2 * 128 + tx + 16 * q) * 2]);
#pragma unroll
            for (int r = 0; r < 4; r++)
#pragma unroll
                for (int q = 0; q < 8; q++) fma2(acc[r][q], aa[r], bb[q]);
        }
        __syncthreads();
    }

    // -------- epilogue --------
#pragma unroll
    for (int r = 0; r < 4; r++) {
        int row = bt * 64 + 4 * ty + r;
#pragma unroll
        for (int q = 0; q < 8; q++) {
            int c = tx + 16 * q;
            unsigned long long u = acc[r][q];
            float lo = __uint_as_float((unsigned)u);
            float hi = __uint_as_float((unsigned)(u >> 32));
            out[row * 128 + c] = lo + hi + b1[c];
        }
    }
}

// ---------------- launch ----------------
extern "C" void kernel_launch(void* const* d_in, const int* in_sizes, int n_in,
                              void* d_out, int out_size) {
    const int*   map_latent = (const int*)d_in[0];
    const float* heading    = (const float*)d_in[1];
    const float* position   = (const float*)d_in[2];
    const float* tokenizer  = (const float*)d_in[3];
    const float* mpl        = (const float*)d_in[4];
    const float* ape_w0 = (const float*)d_in[5];
    const float* ape_b0 = (const float*)d_in[6];
    const float* ape_g0 = (const float*)d_in[7];
    const float* ape_t0 = (const float*)d_in[8];
    const float* ape_w1 = (const float*)d_in[9];
    const float* ape_b1 = (const float*)d_in[10];
    const float* ape_g1 = (const float*)d_in[11];
    const float* ape_t1 = (const float*)d_in[12];
    const float* ape_w2 = (const float*)d_in[13];
    const float* ape_b2 = (const float*)d_in[14];
    const float* mla_w0 = (const float*)d_in[15];
    const float* mla_b0 = (const float*)d_in[16];
    const float* mla_g0 = (const float*)d_in[17];
    const float* mla_t0 = (const float*)d_in[18];
    const float* mla_w1 = (const float*)d_in[19];
    const float* mla_b1 = (const float*)d_in[20];
    const float* mpm_w0 = (const float*)d_in[21];
    const float* mpm_b0 = (const float*)d_in[22];
    const float* mpm_g0 = (const float*)d_in[23];
    const float* mpm_t0 = (const float*)d_in[24];
    const float* mpm_w1 = (const float*)d_in[25];
    const float* mpm_b1 = (const float*)d_in[26];
    float* out = (float*)d_out;

    cudaFuncSetAttribute(k_main, cudaFuncAttributeMaxDynamicSharedMemorySize, SMEM_BYTES);

    k_mp<<<64, 128>>>(mpl, mpm_w0, mpm_b0, mpm_g0, mpm_t0, mpm_w1, mpm_b1, mla_w0);
    k_cb<<<128, 128>>>(tokenizer, mla_w0);
    k_ape<<<8192, 128>>>(heading, position,
                         ape_w0, ape_b0, ape_g0, ape_t0,
                         ape_w1, ape_b1, ape_g1, ape_t1,
                         ape_w2, ape_b2, mla_w0, mla_b0);
    k_main<<<8192, 256, SMEM_BYTES>>>(map_latent, mla_w1, mla_b1, mla_g0, mla_t0, out);
}

// round 7
// speedup vs baseline: 1.2020x; 1.2020x over previous
#include <cuda_runtime.h>
#include <cuda_bf16.h>
#include <cstdint>
#include <math.h>

#define LN_EPS 1e-5f

// ---------------- device scratch ----------------
__device__ float g_CB0[128 * 512];      // codebook @ mla_w0
__device__ float g_MP0[64 * 512];       // map_pos_embed @ mla_w0
__device__ float g_AP0[8192 * 512];     // agent_pos_embed @ mla_w0 + mla_b0
__device__ uint32_t g_Wf[65536];        // W1 fragment-packed bf16 hi/lo: [c4][s8][plane2][nf16][lane32][r2]

// ---------------- helpers ----------------
__device__ __forceinline__ uint32_t smem_u32(const void* p) {
    uint32_t a;
    asm("{ .reg .u64 t; cvta.to.shared.u64 t, %1; cvt.u32.u64 %0, t; }" : "=r"(a) : "l"(p));
    return a;
}

__device__ __forceinline__ void ldsm4(uint32_t (&r)[4], uint32_t addr) {
    asm volatile("ldmatrix.sync.aligned.m8n8.x4.shared.b16 {%0,%1,%2,%3}, [%4];"
        : "=r"(r[0]), "=r"(r[1]), "=r"(r[2]), "=r"(r[3]) : "r"(addr));
}

__device__ __forceinline__ void mma_bf16(float (&d)[4], const uint32_t (&a)[4], uint2 b) {
    asm volatile("mma.sync.aligned.m16n8k16.row.col.f32.bf16.bf16.f32 "
        "{%0,%1,%2,%3}, {%4,%5,%6,%7}, {%8,%9}, {%0,%1,%2,%3};"
        : "+f"(d[0]), "+f"(d[1]), "+f"(d[2]), "+f"(d[3])
        : "r"(a[0]), "r"(a[1]), "r"(a[2]), "r"(a[3]), "r"(b.x), "r"(b.y));
}

__device__ __forceinline__ void blockReduce2_128(float& s, float& s2, float* red) {
#pragma unroll
    for (int off = 16; off > 0; off >>= 1) {
        s  += __shfl_xor_sync(0xffffffffu, s,  off);
        s2 += __shfl_xor_sync(0xffffffffu, s2, off);
    }
    int w = threadIdx.x >> 5;
    if ((threadIdx.x & 31) == 0) { red[w] = s; red[4 + w] = s2; }
    __syncthreads();
    s  = red[0] + red[1] + red[2] + red[3];
    s2 = red[4] + red[5] + red[6] + red[7];
    __syncthreads();
}

// ---------------- kernel: map_pos_embed MLP + projection (verified R1) ----------------
__global__ __launch_bounds__(128) void k_mp(
    const float* __restrict__ mpl,
    const float* __restrict__ w0, const float* __restrict__ b0,
    const float* __restrict__ g0, const float* __restrict__ t0,
    const float* __restrict__ w1, const float* __restrict__ b1,
    const float* __restrict__ W0mla)
{
    __shared__ float xs[256], hs[128], mp[128], red[8];
    int m = blockIdx.x, j = threadIdx.x;
    xs[j] = mpl[m * 256 + j];
    xs[128 + j] = mpl[m * 256 + 128 + j];
    __syncthreads();

    float z = b0[j];
#pragma unroll 8
    for (int i = 0; i < 256; i++) z = fmaf(xs[i], w0[i * 128 + j], z);
    float s = z, s2 = z * z;
    blockReduce2_128(s, s2, red);
    float mean = s * (1.f / 128.f);
    float var = s2 * (1.f / 128.f) - mean * mean;
    float rs = rsqrtf(var + LN_EPS);
    hs[j] = fmaxf((z - mean) * rs * g0[j] + t0[j], 0.f);
    __syncthreads();

    float z1 = b1[j];
#pragma unroll 8
    for (int i = 0; i < 128; i++) z1 = fmaf(hs[i], w1[i * 128 + j], z1);
    mp[j] = z1;
    __syncthreads();

#pragma unroll
    for (int q = 0; q < 4; q++) {
        int c = j + q * 128;
        float acc = 0.f;
#pragma unroll 8
        for (int i = 0; i < 128; i++) acc = fmaf(mp[i], W0mla[i * 512 + c], acc);
        g_MP0[m * 512 + c] = acc;
    }
}

// ---------------- kernel: codebook @ mla_w0 (verified R1) ----------------
__global__ __launch_bounds__(128) void k_cb(
    const float* __restrict__ tok, const float* __restrict__ W0mla)
{
    __shared__ float cb[128];
    int lat = blockIdx.x, j = threadIdx.x;
    cb[j] = tok[lat * 128 + j];
    __syncthreads();
#pragma unroll
    for (int q = 0; q < 4; q++) {
        int c = j + q * 128;
        float acc = 0.f;
#pragma unroll 8
        for (int i = 0; i < 128; i++) acc = fmaf(cb[i], W0mla[i * 512 + c], acc);
        g_CB0[lat * 512 + c] = acc;
    }
}

// ---------------- kernel: agent_pos_emb MLP + projection (verified R1) ----------------
__global__ __launch_bounds__(128) void k_ape(
    const float* __restrict__ heading, const float* __restrict__ position,
    const float* __restrict__ w0, const float* __restrict__ b0,
    const float* __restrict__ g0, const float* __restrict__ t0,
    const float* __restrict__ w1, const float* __restrict__ b1,
    const float* __restrict__ g1, const float* __restrict__ t1,
    const float* __restrict__ w2, const float* __restrict__ b2,
    const float* __restrict__ W0mla, const float* __restrict__ b0mla)
{
    __shared__ float a1[128], a2[128], av[128], red[8];
    int bt = blockIdx.x;
    int b = bt >> 7, t = bt & 127;
    int j = threadIdx.x;

    float hd = heading[(b * 32) * 128 + t];
    float px = position[((b * 32) * 128 + t) * 2 + 0];
    float py = position[((b * 32) * 128 + t) * 2 + 1];
    float sh = sinf(hd), ch = cosf(hd);

    float z = b0[j];
    z = fmaf(px, w0[0 * 128 + j], z);
    z = fmaf(py, w0[1 * 128 + j], z);
    z = fmaf(hd, w0[2 * 128 + j], z);
    z = fmaf(sh, w0[3 * 128 + j], z);
    z = fmaf(ch, w0[4 * 128 + j], z);
    float s = z, s2 = z * z;
    blockReduce2_128(s, s2, red);
    float mean = s * (1.f / 128.f);
    float var = s2 * (1.f / 128.f) - mean * mean;
    float rs = rsqrtf(var + LN_EPS);
    a1[j] = fmaxf((z - mean) * rs * g0[j] + t0[j], 0.f);
    __syncthreads();

    float z1 = b1[j];
#pragma unroll 8
    for (int i = 0; i < 128; i++) z1 = fmaf(a1[i], w1[i * 128 + j], z1);
    s = z1; s2 = z1 * z1;
    blockReduce2_128(s, s2, red);
    mean = s * (1.f / 128.f);
    var = s2 * (1.f / 128.f) - mean * mean;
    rs = rsqrtf(var + LN_EPS);
    a2[j] = fmaxf((z1 - mean) * rs * g1[j] + t1[j], 0.f);
    __syncthreads();

    float z2 = b2[j];
#pragma unroll 8
    for (int i = 0; i < 128; i++) z2 = fmaf(a2[i], w2[i * 128 + j], z2);
    av[j] = z2;
    __syncthreads();

#pragma unroll
    for (int q = 0; q < 4; q++) {
        int c = j + q * 128;
        float acc = b0mla[c];
#pragma unroll 8
        for (int i = 0; i < 128; i++) acc = fmaf(av[i], W0mla[i * 512 + c], acc);
        g_AP0[bt * 512 + c] = acc;
    }
}

// ---------------- kernel: pack W1 into mma-fragment order, bf16 hi/lo ----------------
// flat index per chunk (uint32): (((s*2+plane)*16 + nf)*32 + lane)*2 + r ; chunk offset c*16384
__global__ __launch_bounds__(256) void k_wt(const float* __restrict__ W1) {
    int idx = blockIdx.x * 256 + threadIdx.x;     // 32768 total
    int r    = idx & 1;
    int lane = (idx >> 1) & 31;
    int nf   = (idx >> 6) & 15;
    int s    = (idx >> 10) & 7;
    int c    = (idx >> 13) & 3;
    int k_loc = s * 16 + (lane & 3) * 2 + r * 8;
    int col   = nf * 8 + (lane >> 2);
    int kg    = c * 128 + k_loc;
    float v0 = W1[kg * 128 + col];
    float v1 = W1[(kg + 1) * 128 + col];
    uint32_t u0 = __float_as_uint(v0), u1 = __float_as_uint(v1);
    uint32_t hi = (u0 >> 16) | (u1 & 0xFFFF0000u);
    float l0 = v0 - __uint_as_float(u0 & 0xFFFF0000u);
    float l1 = v1 - __uint_as_float(u1 & 0xFFFF0000u);
    __nv_bfloat162 lp = __floats2bfloat162_rn(l0, l1);
    int base = c * 16384;
    g_Wf[base + (((s * 2 + 0) * 16 + nf) * 32 + lane) * 2 + r] = hi;
    g_Wf[base + (((s * 2 + 1) * 16 + nf) * 32 + lane) * 2 + r] = *(uint32_t*)&lp;
}

// ---------------- main kernel: gather + LN + HMMA (mma.sync bf16 hi/lo 3-pass) ----------------
// grid 4096 (2 bt = 128 rows each), 256 threads = 8 warps (4 row-groups x 2 col-groups)
#define SOFF_HHI  0
#define SOFF_HLO  32768
#define SOFF_B    65536
#define SOFF_AP   131072
#define SOFF_GS   135168
#define SOFF_TS   137216
#define SOFF_LAT  139264
#define SOFF_MEAN 139776
#define SOFF_RS   140288
#define SOFF_B1   140800
#define SMEM_BYTES 141312

__global__ __launch_bounds__(256) void k_main(
    const int* __restrict__ lat_idx,
    const float* __restrict__ b1,
    const float* __restrict__ g0, const float* __restrict__ t0,
    float* __restrict__ out)
{
    extern __shared__ char smem[];
    float* ap_s   = (float*)(smem + SOFF_AP);
    float* gs_s   = (float*)(smem + SOFF_GS);
    float* ts_s   = (float*)(smem + SOFF_TS);
    int*   lat_s  = (int*)(smem + SOFF_LAT);
    float* mean_s = (float*)(smem + SOFF_MEAN);
    float* rs_s   = (float*)(smem + SOFF_RS);
    float* b1_s   = (float*)(smem + SOFF_B1);
    uint2* B2     = (uint2*)(smem + SOFF_B);

    int tid = threadIdx.x, wid = tid >> 5, lane = tid & 31;
    int p = blockIdx.x;

    for (int i = tid; i < 1024; i += 256) ap_s[i] = g_AP0[p * 1024 + i];
    for (int i = tid; i < 512; i += 256) { gs_s[i] = g0[i]; ts_s[i] = t0[i]; }
    if (tid < 128) {
        lat_s[tid] = lat_idx[p * 128 + tid];
        b1_s[tid] = b1[tid];
    }
    __syncthreads();

    // ---- LN stats: row = tid>>1, half = tid&1 ----
    {
        int r = tid >> 1, ht = tid & 1;
        const float4* c4 = (const float4*)(g_CB0 + lat_s[r] * 512 + ht * 256);
        const float4* m4 = (const float4*)(g_MP0 + (r & 63) * 512 + ht * 256);
        const float4* a4 = (const float4*)(ap_s + (r >> 6) * 512 + ht * 256);
        float s = 0.f, s2 = 0.f;
#pragma unroll 8
        for (int i = 0; i < 64; i++) {
            float4 a = c4[i], b = m4[i], e = a4[i];
            float x0 = a.x + b.x + e.x, x1 = a.y + b.y + e.y;
            float x2 = a.z + b.z + e.z, x3 = a.w + b.w + e.w;
            s += x0 + x1 + x2 + x3;
            s2 += x0 * x0 + x1 * x1 + x2 * x2 + x3 * x3;
        }
        s += __shfl_xor_sync(0xffffffffu, s, 1);
        s2 += __shfl_xor_sync(0xffffffffu, s2, 1);
        if (ht == 0) {
            float mean = s * (1.f / 512.f);
            float var = s2 * (1.f / 512.f) - mean * mean;
            mean_s[r] = mean;
            rs_s[r] = rsqrtf(var + LN_EPS);
        }
    }
    __syncthreads();

    // warp tiling
    int rg = wid >> 1, cg = wid & 1;
    int R = rg * 32;
    // ldmatrix lane address components
    int mat = lane >> 3, rl = lane & 7;
    int rowA0 = R + ((mat & 1) << 3) + rl;    // rt=0 tile; rt=1 adds 16
    uint32_t sbH = smem_u32(smem) + SOFF_HHI;
    uint32_t sbL = smem_u32(smem) + SOFF_HLO;

    float acc0[8][4], acc1[8][4];
#pragma unroll
    for (int nf = 0; nf < 8; nf++)
#pragma unroll
        for (int i = 0; i < 4; i++) { acc0[nf][i] = 0.f; acc1[nf][i] = 0.f; }

    int rowB = tid & 127;       // row this thread builds
    int gH = tid >> 7;          // k-half (64 k's)
    const float* cbp = g_CB0 + lat_s[rowB] * 512;
    const float* mpp = g_MP0 + (rowB & 63) * 512;
    const float* app = ap_s + (rowB >> 6) * 512;

    for (int c = 0; c < 4; c++) {
        // ---- copy W frag chunk (64KB) ----
        {
            const uint4* src = (const uint4*)(g_Wf + c * 16384);
            uint4* dst = (uint4*)(smem + SOFF_B);
#pragma unroll
            for (int i = 0; i < 16; i++) dst[i * 256 + tid] = src[i * 256 + tid];
        }
        // ---- build H chunk hi/lo bf16 tiles (swizzled for ldmatrix) ----
        {
            float mean = mean_s[rowB], rsv = rs_s[rowB];
#pragma unroll
            for (int ul = 0; ul < 8; ul++) {
                int u = gH * 8 + ul;
                int kg = c * 128 + u * 8;
                float4 A0 = *(const float4*)(cbp + kg);
                float4 A1 = *(const float4*)(cbp + kg + 4);
                float4 B0 = *(const float4*)(mpp + kg);
                float4 B1 = *(const float4*)(mpp + kg + 4);
                float4 E0 = *(const float4*)(app + kg);
                float4 E1 = *(const float4*)(app + kg + 4);
                float4 G0 = *(const float4*)(gs_s + kg);
                float4 G1 = *(const float4*)(gs_s + kg + 4);
                float4 T0 = *(const float4*)(ts_s + kg);
                float4 T1 = *(const float4*)(ts_s + kg + 4);
                float h[8];
                h[0] = fmaxf(fmaf((A0.x + B0.x + E0.x - mean) * rsv, G0.x, T0.x), 0.f);
                h[1] = fmaxf(fmaf((A0.y + B0.y + E0.y - mean) * rsv, G0.y, T0.y), 0.f);
                h[2] = fmaxf(fmaf((A0.z + B0.z + E0.z - mean) * rsv, G0.z, T0.z), 0.f);
                h[3] = fmaxf(fmaf((A0.w + B0.w + E0.w - mean) * rsv, G0.w, T0.w), 0.f);
                h[4] = fmaxf(fmaf((A1.x + B1.x + E1.x - mean) * rsv, G1.x, T1.x), 0.f);
                h[5] = fmaxf(fmaf((A1.y + B1.y + E1.y - mean) * rsv, G1.y, T1.y), 0.f);
                h[6] = fmaxf(fmaf((A1.z + B1.z + E1.z - mean) * rsv, G1.z, T1.z), 0.f);
                h[7] = fmaxf(fmaf((A1.w + B1.w + E1.w - mean) * rsv, G1.w, T1.w), 0.f);
                uint4 hv, lv;
                uint32_t uu[8];
#pragma unroll
                for (int i = 0; i < 8; i++) uu[i] = __float_as_uint(h[i]);
                hv.x = (uu[0] >> 16) | (uu[1] & 0xFFFF0000u);
                hv.y = (uu[2] >> 16) | (uu[3] & 0xFFFF0000u);
                hv.z = (uu[4] >> 16) | (uu[5] & 0xFFFF0000u);
                hv.w = (uu[6] >> 16) | (uu[7] & 0xFFFF0000u);
                float lo[8];
#pragma unroll
                for (int i = 0; i < 8; i++) lo[i] = h[i] - __uint_as_float(uu[i] & 0xFFFF0000u);
                __nv_bfloat162 p0 = __floats2bfloat162_rn(lo[0], lo[1]);
                __nv_bfloat162 p1 = __floats2bfloat162_rn(lo[2], lo[3]);
                __nv_bfloat162 p2 = __floats2bfloat162_rn(lo[4], lo[5]);
                __nv_bfloat162 p3 = __floats2bfloat162_rn(lo[6], lo[7]);
                lv.x = *(uint32_t*)&p0; lv.y = *(uint32_t*)&p1;
                lv.z = *(uint32_t*)&p2; lv.w = *(uint32_t*)&p3;
                uint32_t sw = (uint32_t)rowB * 256 + (uint32_t)((u ^ (rowB & 7)) << 4);
                *(uint4*)(smem + SOFF_HHI + sw) = hv;
                *(uint4*)(smem + SOFF_HLO + sw) = lv;
            }
        }
        __syncthreads();

        // ---- mma over this chunk ----
#pragma unroll
        for (int s = 0; s < 8; s++) {
            uint32_t ah0[4], ah1[4], al0[4], al1[4];
            int u0 = s * 2 + (mat >> 1);
            int r0 = rowA0, r1 = rowA0 + 16;
            uint32_t off0 = (uint32_t)r0 * 256 + (uint32_t)((u0 ^ (r0 & 7)) << 4);
            uint32_t off1 = (uint32_t)r1 * 256 + (uint32_t)((u0 ^ (r1 & 7)) << 4);
            ldsm4(ah0, sbH + off0);
            ldsm4(ah1, sbH + off1);
            ldsm4(al0, sbL + off0);
            ldsm4(al1, sbL + off1);
#pragma unroll
            for (int nf = 0; nf < 8; nf++) {
                int nfg = cg * 8 + nf;
                uint2 bh = B2[((s * 2 + 0) * 16 + nfg) * 32 + lane];
                uint2 bl = B2[((s * 2 + 1) * 16 + nfg) * 32 + lane];
                mma_bf16(acc0[nf], ah0, bh);
                mma_bf16(acc1[nf], ah1, bh);
                mma_bf16(acc0[nf], ah0, bl);
                mma_bf16(acc1[nf], ah1, bl);
                mma_bf16(acc0[nf], al0, bh);
                mma_bf16(acc1[nf], al1, bh);
            }
        }
        __syncthreads();
    }

    // ---- epilogue ----
    {
        int r0 = R + (lane >> 2);
        int colb = cg * 64 + (lane & 3) * 2;
        long rowg = (long)p * 128;
#pragma unroll
        for (int nf = 0; nf < 8; nf++) {
            int col = colb + nf * 8;
            float ba = b1_s[col], bb = b1_s[col + 1];
            float* o0 = out + (rowg + r0) * 128 + col;
            *(float2*)o0 = make_float2(acc0[nf][0] + ba, acc0[nf][1] + bb);
            *(float2*)(o0 + 8 * 128) = make_float2(acc0[nf][2] + ba, acc0[nf][3] + bb);
            float* o1 = out + (rowg + r0 + 16) * 128 + col;
            *(float2*)o1 = make_float2(acc1[nf][0] + ba, acc1[nf][1] + bb);
            *(float2*)(o1 + 8 * 128) = make_float2(acc1[nf][2] + ba, acc1[nf][3] + bb);
        }
    }
}

// ---------------- launch ----------------
extern "C" void kernel_launch(void* const* d_in, const int* in_sizes, int n_in,
                              void* d_out, int out_size) {
    const int*   map_latent = (const int*)d_in[0];
    const float* heading    = (const float*)d_in[1];
    const float* position   = (const float*)d_in[2];
    const float* tokenizer  = (const float*)d_in[3];
    const float* mpl        = (const float*)d_in[4];
    const float* ape_w0 = (const float*)d_in[5];
    const float* ape_b0 = (const float*)d_in[6];
    const float* ape_g0 = (const float*)d_in[7];
    const float* ape_t0 = (const float*)d_in[8];
    const float* ape_w1 = (const float*)d_in[9];
    const float* ape_b1 = (const float*)d_in[10];
    const float* ape_g1 = (const float*)d_in[11];
    const float* ape_t1 = (const float*)d_in[12];
    const float* ape_w2 = (const float*)d_in[13];
    const float* ape_b2 = (const float*)d_in[14];
    const float* mla_w0 = (const float*)d_in[15];
    const float* mla_b0 = (const float*)d_in[16];
    const float* mla_g0 = (const float*)d_in[17];
    const float* mla_t0 = (const float*)d_in[18];
    const float* mla_w1 = (const float*)d_in[19];
    const float* mla_b1 = (const float*)d_in[20];
    const float* mpm_w0 = (const float*)d_in[21];
    const float* mpm_b0 = (const float*)d_in[22];
    const float* mpm_g0 = (const float*)d_in[23];
    const float* mpm_t0 = (const float*)d_in[24];
    const float* mpm_w1 = (const float*)d_in[25];
    const float* mpm_b1 = (const float*)d_in[26];
    float* out = (float*)d_out;

    cudaFuncSetAttribute(k_main, cudaFuncAttributeMaxDynamicSharedMemorySize, SMEM_BYTES);

    k_mp<<<64, 128>>>(mpl, mpm_w0, mpm_b0, mpm_g0, mpm_t0, mpm_w1, mpm_b1, mla_w0);
    k_cb<<<128, 128>>>(tokenizer, mla_w0);
    k_wt<<<128, 256>>>(mla_w1);
    k_ape<<<8192, 128>>>(heading, position,
                         ape_w0, ape_b0, ape_g0, ape_t0,
                         ape_w1, ape_b1, ape_g1, ape_t1,
                         ape_w2, ape_b2, mla_w0, mla_b0);
    k_main<<<4096, 256, SMEM_BYTES>>>(map_latent, mla_b1, mla_g0, mla_t0, out);
}